// round 2
// baseline (speedup 1.0000x reference)
#include <cuda_runtime.h>
#include <math.h>
#include <float.h>

// ---------------- problem constants ----------------
// layers: C = {64,128,256,512}, HW = {3136,784,196,49}, B=256, R=2000
#define NB 256
#define NR 2000
#define NRP 2048           // padded R for aligned float4 stores

__constant__ int c_C[4]      = {64, 128, 256, 512};
__constant__ int c_HW[4]     = {3136, 784, 196, 49};
__constant__ int c_qoff[4]   = {0, 16384, 49152, 114688};   // 256*cumsum(C)

// ---------------- scratch (static device globals; no allocation) ----------------
__device__ __align__(16) float g_fq[245760];                 // pooled queries, [layer][b][c] flat
__device__ __align__(16) float g_dot[4 * NB * NRP];          // q . ref^T, padded
__device__ float g_r2[4 * NR];                               // ||ref||^2
__device__ float g_q2[4 * NB];                               // ||q||^2
__device__ float g_lid[NB * 4];                              // LID features

// ---------------- kernel 1: spatial mean pooling (warp per (b,c) row) ----------------
__global__ void __launch_bounds__(256) pool_kernel(
    const float* __restrict__ f0, const float* __restrict__ f1,
    const float* __restrict__ f2, const float* __restrict__ f3)
{
    int gw   = (blockIdx.x * 256 + threadIdx.x) >> 5;
    int lane = threadIdx.x & 31;
    if (gw >= 245760) return;

    int l, base;
    if      (gw < 16384)  { l = 0; base = 0; }
    else if (gw < 49152)  { l = 1; base = 16384; }
    else if (gw < 114688) { l = 2; base = 49152; }
    else                  { l = 3; base = 114688; }
    int row = gw - base;                       // row = b*C + c
    const float* f = (l == 0) ? f0 : (l == 1) ? f1 : (l == 2) ? f2 : f3;
    int HW = c_HW[l];
    const float* src = f + (size_t)row * HW;

    float s = 0.f;
    if (l < 3) {
        // HW divisible by 4 and row byte-stride is 16B-multiple for layers 0..2
        const float4* s4 = (const float4*)src;
        int n4 = HW >> 2;
        for (int i = lane; i < n4; i += 32) {
            float4 v = s4[i];
            s += (v.x + v.y) + (v.z + v.w);
        }
    } else {
        for (int i = lane; i < HW; i += 32) s += src[i];
    }
    #pragma unroll
    for (int o = 16; o > 0; o >>= 1) s += __shfl_xor_sync(0xffffffffu, s, o);
    if (lane == 0) g_fq[c_qoff[l] + row] = s / (float)HW;
}

// ---------------- kernel 2: squared norms of refs and pooled queries ----------------
__global__ void __launch_bounds__(256) norms_kernel(
    const float* __restrict__ r0, const float* __restrict__ r1,
    const float* __restrict__ r2, const float* __restrict__ r3)
{
    int gw   = (blockIdx.x * 256 + threadIdx.x) >> 5;
    int lane = threadIdx.x & 31;
    if (gw >= 9024) return;   // 4*2000 ref rows + 4*256 query rows

    const float* src;
    float* out;
    int C;
    if (gw < 8000) {
        int l = gw / NR, row = gw % NR;
        const float* rp = (l == 0) ? r0 : (l == 1) ? r1 : (l == 2) ? r2 : r3;
        C = c_C[l];
        src = rp + (size_t)row * C;
        out = g_r2 + l * NR + row;
    } else {
        int idx = gw - 8000;
        int l = idx >> 8, row = idx & 255;
        C = c_C[l];
        src = g_fq + c_qoff[l] + (size_t)row * C;
        out = g_q2 + l * NB + row;
    }
    float s = 0.f;
    const float4* s4 = (const float4*)src;
    int n4 = C >> 2;
    for (int i = lane; i < n4; i += 32) {
        float4 v = s4[i];
        s += v.x * v.x + v.y * v.y + v.z * v.z + v.w * v.w;
    }
    #pragma unroll
    for (int o = 16; o > 0; o >>= 1) s += __shfl_xor_sync(0xffffffffu, s, o);
    if (lane == 0) *out = s;
}

// ---------------- kernel 3: dot products q . ref^T (tiled, 32x64 per block) ----------------
__global__ void __launch_bounds__(256) dist_gemm_kernel(
    const float* __restrict__ r0, const float* __restrict__ r1,
    const float* __restrict__ r2, const float* __restrict__ r3)
{
    int l = blockIdx.z;
    int C = c_C[l];
    const float* ref = (l == 0) ? r0 : (l == 1) ? r1 : (l == 2) ? r2 : r3;
    const float* q   = g_fq + c_qoff[l];

    int bt = blockIdx.y << 5;   // batch tile base (32)
    int rt = blockIdx.x << 6;   // ref tile base (64)

    __shared__ float qs[16][33];                   // [k][b], padded (conflict-free)
    __shared__ __align__(16) float rs[16][68];     // [k][r], 272B rows keep float4 align

    int tx = threadIdx.x, ty = threadIdx.y;
    int tid = ty * 16 + tx;

    float acc[2][4];
    #pragma unroll
    for (int i = 0; i < 2; i++)
        #pragma unroll
        for (int j = 0; j < 4; j++) acc[i][j] = 0.f;

    for (int c0 = 0; c0 < C; c0 += 16) {
        #pragma unroll
        for (int i = 0; i < 2; i++) {
            int idx = tid + i * 256;
            int b = idx >> 4, kk = idx & 15;
            qs[kk][b] = q[(size_t)(bt + b) * C + c0 + kk];
        }
        #pragma unroll
        for (int i = 0; i < 4; i++) {
            int idx = tid + i * 256;
            int r = idx >> 4, kk = idx & 15;
            int rr = rt + r;
            rs[kk][r] = (rr < NR) ? ref[(size_t)rr * C + c0 + kk] : 0.f;
        }
        __syncthreads();
        #pragma unroll
        for (int kk = 0; kk < 16; kk++) {
            float q0 = qs[kk][ty * 2];
            float q1 = qs[kk][ty * 2 + 1];
            float4 rv = *(const float4*)&rs[kk][tx * 4];
            acc[0][0] += q0 * rv.x; acc[0][1] += q0 * rv.y;
            acc[0][2] += q0 * rv.z; acc[0][3] += q0 * rv.w;
            acc[1][0] += q1 * rv.x; acc[1][1] += q1 * rv.y;
            acc[1][2] += q1 * rv.z; acc[1][3] += q1 * rv.w;
        }
        __syncthreads();
    }

    float* out = g_dot + ((size_t)l * NB + bt) * NRP + rt;
    #pragma unroll
    for (int i = 0; i < 2; i++) {
        int b = ty * 2 + i;
        *(float4*)&out[(size_t)b * NRP + tx * 4] =
            make_float4(acc[i][0], acc[i][1], acc[i][2], acc[i][3]);
    }
}

// ---------------- kernel 4: top-(k+1) smallest distances + LID per (b, layer) ----------------
__global__ void __launch_bounds__(256) select_kernel(const int* __restrict__ kp)
{
    int b = blockIdx.x;
    int l = blockIdx.y;
    int tid = threadIdx.x;

    __shared__ float sd[NR];
    __shared__ float rv[256];
    __shared__ int   ri[256];
    __shared__ float topd[64];

    float q2v = g_q2[l * NB + b];
    const float* dotp = g_dot + ((size_t)l * NB + b) * NRP;
    const float* r2p  = g_r2 + l * NR;

    for (int r = tid; r < NR; r += 256)
        sd[r] = q2v + r2p[r] - 2.f * dotp[r];
    __syncthreads();

    int kk  = *kp;
    int kp1 = min(kk + 1, 63);

    for (int t = 0; t < kp1; t++) {
        float best = FLT_MAX; int bi = 0;
        for (int r = tid; r < NR; r += 256) {
            float v = sd[r];
            if (v < best) { best = v; bi = r; }
        }
        rv[tid] = best; ri[tid] = bi;
        __syncthreads();
        for (int s = 128; s > 0; s >>= 1) {
            if (tid < s && rv[tid + s] < rv[tid]) {
                rv[tid] = rv[tid + s]; ri[tid] = ri[tid + s];
            }
            __syncthreads();
        }
        if (tid == 0) { topd[t] = rv[0]; sd[ri[0]] = FLT_MAX; }
        __syncthreads();
    }

    if (tid == 0) {
        // drop the nearest (topd[0]); use topd[1..k] ascending, d_k = topd[k]
        float dk = sqrtf(fmaxf(topd[kp1 - 1], 0.f));
        float s = 0.f;
        for (int i = 1; i < kp1; i++) {
            float di = sqrtf(fmaxf(topd[i], 0.f));
            s += logf(di / dk);
        }
        g_lid[b * 4 + l] = -(float)kk / s;
    }
}

// ---------------- kernel 5: linear head + sigmoid ----------------
__global__ void final_kernel(const float* __restrict__ w,
                             const float* __restrict__ bb,
                             float* __restrict__ out)
{
    int b = threadIdx.x;
    float z = bb[0];
    #pragma unroll
    for (int j = 0; j < 4; j++) z += g_lid[b * 4 + j] * w[j];
    out[b] = 1.f / (1.f + expf(-z));
}

// ---------------- launch ----------------
extern "C" void kernel_launch(void* const* d_in, const int* in_sizes, int n_in,
                              void* d_out, int out_size)
{
    const float* feat[4] = {0, 0, 0, 0};
    const float* ref[4]  = {0, 0, 0, 0};
    const float* rw = 0;
    const float* rb = 0;
    const int*   kp = 0;
    int ones = 0;
    for (int i = 0; i < n_in; i++) {
        switch (in_sizes[i]) {
            case 51380224: feat[0] = (const float*)d_in[i]; break;
            case 25690112: feat[1] = (const float*)d_in[i]; break;
            case 12845056: feat[2] = (const float*)d_in[i]; break;
            case 6422528:  feat[3] = (const float*)d_in[i]; break;
            case 128000:   ref[0]  = (const float*)d_in[i]; break;
            case 256000:   ref[1]  = (const float*)d_in[i]; break;
            case 512000:   ref[2]  = (const float*)d_in[i]; break;
            case 1024000:  ref[3]  = (const float*)d_in[i]; break;
            case 4:        rw      = (const float*)d_in[i]; break;
            case 1:
                if (ones++ == 0) rb = (const float*)d_in[i];
                else             kp = (const int*)d_in[i];
                break;
            default: break;
        }
    }

    // 1) pooling: 245760 warps, 8 warps/block
    pool_kernel<<<30720, 256>>>(feat[0], feat[1], feat[2], feat[3]);

    // 2) norms: 9024 warps
    norms_kernel<<<1128, 256>>>(ref[0], ref[1], ref[2], ref[3]);

    // 3) dot products
    dim3 gg(NRP / 64, NB / 32, 4);   // (32, 8, 4)
    dim3 bt(16, 16);
    dist_gemm_kernel<<<gg, bt>>>(ref[0], ref[1], ref[2], ref[3]);

    // 4) selection + LID
    dim3 gs(NB, 4);
    select_kernel<<<gs, 256>>>(kp);

    // 5) head
    final_kernel<<<1, 256>>>(rw, rb, (float*)d_out);
}